// round 3
// baseline (speedup 1.0000x reference)
#include <cuda_runtime.h>

#define VDIM 131072
#define NROWS 1024
#define TPB 1024
#define L2E 1.4426950408889634f
#define LN2 0.6931471805599453f

__device__ float g_ent[NROWS];

__device__ __forceinline__ float ex2f(float x) {
    float y; asm("ex2.approx.f32 %0, %1;" : "=f"(y) : "f"(x)); return y;
}
__device__ __forceinline__ float lg2f(float x) {
    float y; asm("lg2.approx.f32 %0, %1;" : "=f"(y) : "f"(x)); return y;
}

// One CTA per (b, t) row. Single HBM pass: online-softmax accumulators
// m (running max), s (sum exp2(t)), w (sum e*t) with t = (x-m)*log2(e).
__global__ __launch_bounds__(TPB, 1)
void softmax_row_kernel(const float* __restrict__ logits,
                        const int* __restrict__ input_ids,
                        float* __restrict__ out)
{
    const int row = blockIdx.x;
    const int b = row >> 8;
    const int t = row & 255;
    const float* __restrict__ baseF = logits + (size_t)(b * 257 + t) * VDIM;
    const float4* __restrict__ base4 = reinterpret_cast<const float4*>(baseF);
    const int tid = threadIdx.x;

    float m = -1e30f;
    float s0 = 0.f, s1 = 0.f, w0 = 0.f, w1 = 0.f;

    // prefetch iteration 0
    float4 c0 = base4[0 * TPB + tid];
    float4 c1 = base4[1 * TPB + tid];
    float4 c2 = base4[2 * TPB + tid];
    float4 c3 = base4[3 * TPB + tid];

#pragma unroll 1
    for (int i = 0; i < 8; i++) {
        float4 n0 = make_float4(0.f, 0.f, 0.f, 0.f);
        float4 n1 = n0, n2 = n0, n3 = n0;
        if (i < 7) {
            n0 = base4[(i * 4 + 4) * TPB + tid];
            n1 = base4[(i * 4 + 5) * TPB + tid];
            n2 = base4[(i * 4 + 6) * TPB + tid];
            n3 = base4[(i * 4 + 7) * TPB + tid];
        }
        float x[16] = {c0.x, c0.y, c0.z, c0.w, c1.x, c1.y, c1.z, c1.w,
                       c2.x, c2.y, c2.z, c2.w, c3.x, c3.y, c3.z, c3.w};
        float mc = x[0];
#pragma unroll
        for (int j = 1; j < 16; j++) mc = fmaxf(mc, x[j]);
        if (mc > m) {
            float d = (m - mc) * L2E;     // <= 0
            float sc = ex2f(d);
            w0 = sc * fmaf(d, s0, w0);
            w1 = sc * fmaf(d, s1, w1);
            s0 *= sc;
            s1 *= sc;
            m = mc;
        }
        float nm = -m * L2E;
#pragma unroll
        for (int j = 0; j < 16; j += 2) {
            float t0 = fmaf(x[j],     L2E, nm);
            float t1 = fmaf(x[j + 1], L2E, nm);
            float e0 = ex2f(t0);
            float e1 = ex2f(t1);
            s0 += e0;
            s1 += e1;
            w0 = fmaf(e0, t0, w0);
            w1 = fmaf(e1, t1, w1);
        }
        c0 = n0; c1 = n1; c2 = n2; c3 = n3;
    }

    float s = s0 + s1;
    float w = w0 + w1;

    // warp tree-combine of (m, s, w)
#pragma unroll
    for (int off = 16; off; off >>= 1) {
        float m2 = __shfl_down_sync(0xffffffffu, m, off);
        float sB = __shfl_down_sync(0xffffffffu, s, off);
        float wB = __shfl_down_sync(0xffffffffu, w, off);
        float M  = fmaxf(m, m2);
        float d1 = (m  - M) * L2E;
        float d2 = (m2 - M) * L2E;
        float a1 = ex2f(d1);
        float a2 = ex2f(d2);
        w = a1 * fmaf(d1, s, w) + a2 * fmaf(d2, sB, wB);
        s = a1 * s + a2 * sB;
        m = M;
    }

    __shared__ float sm[32], ss[32], sw[32];
    const int lane = tid & 31;
    const int warp = tid >> 5;
    if (lane == 0) { sm[warp] = m; ss[warp] = s; sw[warp] = w; }
    __syncthreads();

    if (warp == 0) {
        m = sm[lane]; s = ss[lane]; w = sw[lane];
#pragma unroll
        for (int off = 16; off; off >>= 1) {
            float m2 = __shfl_down_sync(0xffffffffu, m, off);
            float sB = __shfl_down_sync(0xffffffffu, s, off);
            float wB = __shfl_down_sync(0xffffffffu, w, off);
            float M  = fmaxf(m, m2);
            float d1 = (m  - M) * L2E;
            float d2 = (m2 - M) * L2E;
            float a1 = ex2f(d1);
            float a2 = ex2f(d2);
            w = a1 * fmaf(d1, s, w) + a2 * fmaf(d2, sB, wB);
            s = a1 * s + a2 * sB;
            m = M;
        }
        if (lane == 0) {
            int cid = input_ids[b * 257 + t + 1];
            float chosen = __ldg(baseF + cid);
            float l2s = lg2f(s);
            // log_softmax[chosen] = chosen - (m + ln(S))
            out[1 + row] = chosen - m - LN2 * l2s;
            // entropy = ln2 * (log2 S - W/S)   (eps term negligible: ~1e-4 abs)
            g_ent[row] = LN2 * (l2s - w / s);
        }
    }
}

// Tiny epilogue: loss scalar + per-batch masked entropy means.
__global__ void finalize_kernel(const int* __restrict__ labels,
                                const float* __restrict__ adv,
                                float* __restrict__ out)
{
    __shared__ float s_mfs[4], s_lnum[4];
    const int warp = threadIdx.x >> 5;
    const int lane = threadIdx.x & 31;

    if (warp < 4) {
        const int b = warp;
        const int* __restrict__ lab = labels + b * 257 + 1; // token t -> lab[t]
        const float* __restrict__ ent = g_ent + b * 256;

        int   lv[8];
        float le[8], lm[8];
        int vloc = 0;
#pragma unroll
        for (int i = 0; i < 8; i++) {
            int tt = lane * 8 + i;
            int L = lab[tt];
            lv[i] = (L == 1) ? 1 : 0;
            lm[i] = (float)L;
            le[i] = ent[tt];
            vloc += lv[i];
        }
        // exclusive scan of valid counts across lanes (blocked token order)
        int incl = vloc;
#pragma unroll
        for (int off = 1; off < 32; off <<= 1) {
            int v = __shfl_up_sync(0xffffffffu, incl, off);
            if (lane >= off) incl += v;
        }
        int run = incl - vloc;

        float entw = 0.f, mfs = 0.f, tent = 0.f;
        int tcnt = 0;
#pragma unroll
        for (int i = 0; i < 8; i++) {
            entw += le[i] * lm[i];
            mfs  += lm[i];
            if (lv[i]) {
                run++;
                if (run >= 4 && run <= 100) { tent += le[i]; tcnt++; }
            }
        }
#pragma unroll
        for (int off = 16; off; off >>= 1) {
            entw += __shfl_down_sync(0xffffffffu, entw, off);
            mfs  += __shfl_down_sync(0xffffffffu, mfs,  off);
            tent += __shfl_down_sync(0xffffffffu, tent, off);
            tcnt += __shfl_down_sync(0xffffffffu, tcnt, off);
        }
        if (lane == 0) {
            out[1025 + b] = entw / mfs;
            out[1029 + b] = tent / (float)tcnt;
            s_mfs[b]  = mfs;
            // ratio = exp(logp - stop_grad(logp)) = 1 exactly,
            // clip(1) = 1, so per_token_loss = -adv_b for every token.
            s_lnum[b] = -adv[b] * mfs;
        }
    }
    __syncthreads();
    if (threadIdx.x == 0) {
        float num = s_lnum[0] + s_lnum[1] + s_lnum[2] + s_lnum[3];
        float den = s_mfs[0] + s_mfs[1] + s_mfs[2] + s_mfs[3];
        out[0] = num / den;
    }
}

extern "C" void kernel_launch(void* const* d_in, const int* in_sizes, int n_in,
                              void* d_out, int out_size)
{
    const float* logits    = (const float*)d_in[0];
    const float* adv       = (const float*)d_in[1];
    const int*   input_ids = (const int*)d_in[2];
    const int*   labels    = (const int*)d_in[3];
    float* out = (float*)d_out;

    softmax_row_kernel<<<NROWS, TPB>>>(logits, input_ids, out);
    finalize_kernel<<<1, 128>>>(labels, adv, out);
}